// round 9
// baseline (speedup 1.0000x reference)
#include <cuda_runtime.h>

// Problem constants (fixed shapes for this dataset)
#define T_C 500000
#define M_C 50000
#define B_C 5000
#define D_C 256
#define D4_C 64     // D / 4
#define K_C 100

// Scratch (alloc-free rule: __device__ globals)
__device__ float4 g_men_emb4[(size_t)M_C * D4_C];  // [M, D/4] mention means
__device__ float  g_sel[M_C];                      // [M] selected score
__device__ int    g_wrow[M_C];                     // [M] chosen W row per mention

// ---------------------------------------------------------------------------
// Kernel 0: per-bag argmax over typeTensor row (first-max tie-break like
// jnp.argmax), scatter winning row index to all mentions of the bag.
// 8 warps per block, one warp per bag.
// ---------------------------------------------------------------------------
__global__ void bag_argmax_kernel(const float* __restrict__ typeT,
                                  const int* __restrict__ scope,
                                  int B, int K) {
    int warp = threadIdx.x >> 5;
    int lane = threadIdx.x & 31;
    int b = blockIdx.x * 8 + warp;
    if (b >= B) return;

    float best = -INFINITY;
    int bidx = K;  // sentinel > any real idx
    for (int k = lane; k < K; k += 32) {
        float v = typeT[(size_t)b * K + k];
        if (v > best) { best = v; bidx = k; }  // ascending walk keeps first max
    }
    for (int off = 16; off; off >>= 1) {
        float ov = __shfl_down_sync(0xffffffffu, best, off);
        int   oi = __shfl_down_sync(0xffffffffu, bidx, off);
        if (ov > best || (ov == best && oi < bidx)) { best = ov; bidx = oi; }
    }
    bidx = __shfl_sync(0xffffffffu, bidx, 0);

    int s0 = scope[b], s1 = scope[b + 1];
    for (int m = s0 + lane; m < s1; m += 32) g_wrow[m] = bidx;
}

// ---------------------------------------------------------------------------
// Kernel 1 (dominant): one block (256 thr) per mention.
// 4 token-groups of 64 lanes; each lane holds one float4 (16B) of the row.
// Unroll-4 inside each group -> up to 16 tokens' loads in flight per block.
//   men_emb[m,:] = mean_t Wemb[feat[t],:]
//   sel[m]       = men_emb[m,:] . Wlin[wrow[m],:]
// ---------------------------------------------------------------------------
__global__ void mention_kernel(const int* __restrict__ feat,
                               const int* __restrict__ off,
                               const float4* __restrict__ Wemb4,
                               const float4* __restrict__ Wlin4,
                               int T, int M) {
    int m = blockIdx.x;
    if (m >= M) return;
    int tid = threadIdx.x;
    int g = tid >> 6;   // token group 0..3
    int l = tid & 63;   // float4 lane within row

    int start = off[m];
    int end   = (m + 1 < M) ? off[m + 1] : T;

    float4 acc = make_float4(0.f, 0.f, 0.f, 0.f);
    int t = start + g;
    // unroll-4: 4 independent LDG.128 in flight per thread
    for (; t + 12 < end; t += 16) {
        int v0 = __ldg(&feat[t]);
        int v1 = __ldg(&feat[t + 4]);
        int v2 = __ldg(&feat[t + 8]);
        int v3 = __ldg(&feat[t + 12]);
        float4 e0 = __ldg(&Wemb4[(size_t)v0 * D4_C + l]);
        float4 e1 = __ldg(&Wemb4[(size_t)v1 * D4_C + l]);
        float4 e2 = __ldg(&Wemb4[(size_t)v2 * D4_C + l]);
        float4 e3 = __ldg(&Wemb4[(size_t)v3 * D4_C + l]);
        acc.x += (e0.x + e1.x) + (e2.x + e3.x);
        acc.y += (e0.y + e1.y) + (e2.y + e3.y);
        acc.z += (e0.z + e1.z) + (e2.z + e3.z);
        acc.w += (e0.w + e1.w) + (e2.w + e3.w);
    }
    for (; t < end; t += 4) {
        int v = __ldg(&feat[t]);
        float4 e = __ldg(&Wemb4[(size_t)v * D4_C + l]);
        acc.x += e.x; acc.y += e.y; acc.z += e.z; acc.w += e.w;
    }

    __shared__ float4 s_part[4][D4_C];
    __shared__ float s_red[2];
    s_part[g][l] = acc;
    __syncthreads();

    if (tid < D4_C) {
        float4 a  = s_part[0][tid];
        float4 b1 = s_part[1][tid];
        float4 b2 = s_part[2][tid];
        float4 b3 = s_part[3][tid];
        float inv = 1.0f / (float)(end - start);
        float4 mean;
        mean.x = (a.x + b1.x + b2.x + b3.x) * inv;
        mean.y = (a.y + b1.y + b2.y + b3.y) * inv;
        mean.z = (a.z + b1.z + b2.z + b3.z) * inv;
        mean.w = (a.w + b1.w + b2.w + b3.w) * inv;
        // streaming store: keep embedding table resident in L2
        __stcs(&g_men_emb4[(size_t)m * D4_C + tid], mean);

        int wr = g_wrow[m];
        float4 w = __ldg(&Wlin4[(size_t)wr * D4_C + tid]);
        float p = mean.x * w.x + mean.y * w.y + mean.z * w.z + mean.w * w.w;
        for (int o = 16; o; o >>= 1) p += __shfl_down_sync(0xffffffffu, p, o);
        if ((tid & 31) == 0) s_red[tid >> 5] = p;
    }
    __syncthreads();
    if (tid == 0) g_sel[m] = s_red[0] + s_red[1];
}

// ---------------------------------------------------------------------------
// Kernel 2: one block (256 thr) per bag.
//   softmax over sel within bag -> att; bag_emb = sum att * men_emb;
//   out[b,k] = bag_emb . Wlin[k,:]
// Accumulation uses the same 4-group float4 layout.
// ---------------------------------------------------------------------------
__global__ void bag_kernel(const int* __restrict__ scope,
                           const float* __restrict__ Wlin,
                           int B, int K,
                           float* __restrict__ out) {
    int b = blockIdx.x;
    if (b >= B) return;
    int tid = threadIdx.x;
    int s0 = scope[b], s1 = scope[b + 1];

    __shared__ float s_red[8];
    __shared__ float s_mx, s_sum;
    __shared__ float4 s_part[4][D4_C];
    __shared__ float s_bag[D_C];

    // --- segment max ---
    float mx = -INFINITY;
    for (int m = s0 + tid; m < s1; m += 256) mx = fmaxf(mx, g_sel[m]);
    for (int o = 16; o; o >>= 1) mx = fmaxf(mx, __shfl_down_sync(0xffffffffu, mx, o));
    if ((tid & 31) == 0) s_red[tid >> 5] = mx;
    __syncthreads();
    if (tid == 0) {
        float v = s_red[0];
        #pragma unroll
        for (int i = 1; i < 8; i++) v = fmaxf(v, s_red[i]);
        s_mx = v;
    }
    __syncthreads();
    float mxv = s_mx;

    // --- sum of exp ---
    float se = 0.0f;
    for (int m = s0 + tid; m < s1; m += 256) se += expf(g_sel[m] - mxv);
    for (int o = 16; o; o >>= 1) se += __shfl_down_sync(0xffffffffu, se, o);
    if ((tid & 31) == 0) s_red[tid >> 5] = se;
    __syncthreads();
    if (tid == 0) {
        float v = 0.0f;
        #pragma unroll
        for (int i = 0; i < 8; i++) v += s_red[i];
        s_sum = v;
    }
    __syncthreads();
    float inv_s = 1.0f / s_sum;

    // --- bag_emb = sum att * men_emb  (4 mention-groups x 64-lane float4) ---
    int g = tid >> 6, l = tid & 63;
    float4 acc = make_float4(0.f, 0.f, 0.f, 0.f);
    for (int m = s0 + g; m < s1; m += 4) {
        float a = expf(g_sel[m] - mxv) * inv_s;
        float4 e = __ldcs(&g_men_emb4[(size_t)m * D4_C + l]);  // no reuse
        acc.x += a * e.x; acc.y += a * e.y; acc.z += a * e.z; acc.w += a * e.w;
    }
    s_part[g][l] = acc;
    __syncthreads();
    if (tid < D4_C) {
        float4 a  = s_part[0][tid];
        float4 b1 = s_part[1][tid];
        float4 b2 = s_part[2][tid];
        float4 b3 = s_part[3][tid];
        s_bag[4 * tid + 0] = a.x + b1.x + b2.x + b3.x;
        s_bag[4 * tid + 1] = a.y + b1.y + b2.y + b3.y;
        s_bag[4 * tid + 2] = a.z + b1.z + b2.z + b3.z;
        s_bag[4 * tid + 3] = a.w + b1.w + b2.w + b3.w;
    }
    __syncthreads();

    // --- out[b,k] = bag_emb . Wlin[k,:]  (8 warps cover K) ---
    int warp = tid >> 5, lane = tid & 31;
    for (int k = warp; k < K; k += 8) {
        float p = 0.0f;
        #pragma unroll
        for (int i = 0; i < 8; i++) {
            int dd = lane + 32 * i;
            p += s_bag[dd] * Wlin[(size_t)k * D_C + dd];
        }
        for (int o = 16; o; o >>= 1) p += __shfl_down_sync(0xffffffffu, p, o);
        if (lane == 0) out[(size_t)b * K + k] = p;
    }
}

// ---------------------------------------------------------------------------
extern "C" void kernel_launch(void* const* d_in, const int* in_sizes, int n_in,
                              void* d_out, int out_size) {
    const int*   feat  = (const int*)d_in[0];    // feature_seq [T]
    const int*   off   = (const int*)d_in[1];    // offset_seq  [M]
    const int*   scope = (const int*)d_in[2];    // scope       [B+1]
    const float* typeT = (const float*)d_in[3];  // typeTensor  [B,K]
    const float* Wemb  = (const float*)d_in[4];  // word_embedding [V,D]
    const float* Wlin  = (const float*)d_in[5];  // linear_weight  [K,D]
    float* out = (float*)d_out;

    int T = in_sizes[0];
    int M = in_sizes[1];
    int B = in_sizes[2] - 1;
    int K = in_sizes[3] / B;

    bag_argmax_kernel<<<(B + 7) / 8, 256>>>(typeT, scope, B, K);
    mention_kernel<<<M, 256>>>(feat, off,
                               (const float4*)Wemb, (const float4*)Wlin, T, M);
    bag_kernel<<<B, 256>>>(scope, Wlin, B, K, out);
}